// round 3
// baseline (speedup 1.0000x reference)
#include <cuda_runtime.h>
#include <cuda_bf16.h>

// Shapes (fixed):
//   x:    (512, 128, 64)  fp32
//   mask: (256, 4)        int64-declared, but JAX x64-off makes it int32 —
//                         auto-detected at runtime (see mask_val()).
//   W:    (256, 64, 256)  fp32
//   b:    (256, 64)       fp32
//   out:  (512, 256, 64)  fp32
// out[b,h,o] = sum_d gathered[b,h,d] * W[h,o,d] + bias[h,o]
// gathered[b,h, 64*k + w] = x[b, mask[h,k], w]

namespace asl {

constexpr int B_SZ   = 512;
constexpr int H_IN   = 128;
constexpr int W_IN   = 64;
constexpr int H_OUT  = 256;
constexpr int W_OUT  = 64;
constexpr int KSEL   = 4;
constexpr int D      = W_IN * KSEL;   // 256

constexpr int BM      = 64;           // batch rows per CTA
constexpr int KC      = 64;           // k-chunk (== W_IN)
constexpr int THREADS = 256;          // 16 x 16 threads, 4x4 register tile each
constexpr int P       = 68;           // smem pitch (floats): float4-aligned

// Detect int64-vs-int32 mask layout: if the buffer is int64 (values < 128),
// every odd 32-bit word is 0. With int32 data, 16 consecutive odd-position
// mask values all being zero has probability (1/128)^16 ~ 0.
__device__ __forceinline__ bool mask_is_i64(const int* m32) {
    int acc = 0;
#pragma unroll
    for (int i = 0; i < 16; ++i) acc |= m32[2 * i + 1];
    return acc == 0;
}

__device__ __forceinline__ int mask_val(const int* m32, bool is64, int idx) {
    int v = is64 ? m32[2 * idx] : m32[idx];
    // hard safety clamp: wrong interpretation -> wrong answer, never a crash
    return min(max(v, 0), H_IN - 1);
}

__global__ __launch_bounds__(THREADS, 2)
void sparse_linear_kernel(const float* __restrict__ x,
                          const int* __restrict__ mask32,
                          const float* __restrict__ W,
                          const float* __restrict__ bias,
                          float* __restrict__ out) {
    // k-major transposed tiles: At[k][m], Wt[k][o].  2 * 64*68*4 B = 34 KB.
    __shared__ alignas(16) float At[KC * P];
    __shared__ alignas(16) float Wt[KC * P];

    const int h  = blockIdx.y;
    const int b0 = blockIdx.x * BM;
    const int t  = threadIdx.x;
    const int tx = t & 15;            // output-column group (o = tx*4 .. +3)
    const int ty = t >> 4;            // batch-row group    (m = ty*4 .. +3)

    const bool m64 = mask_is_i64(mask32);

    // Staging coordinates: consecutive threads -> consecutive k (coalesced
    // global reads); smem writes stride P (low-conflict, staging only).
    const int s_r = t >> 6;           // 0..3
    const int s_c = t & 63;           // 0..63

    const float* Wh = W + (size_t)h * W_OUT * D;

    float acc[4][4];
#pragma unroll
    for (int i = 0; i < 4; ++i)
#pragma unroll
        for (int j = 0; j < 4; ++j) acc[i][j] = 0.0f;

#pragma unroll
    for (int kc = 0; kc < KSEL; ++kc) {
        const int xrow = mask_val(mask32, m64, h * KSEL + kc);
        const float* xbase = x + (size_t)xrow * W_IN;

        // ---- Stage Wt[k][o] = W[h][o][kc*64 + k] ----
#pragma unroll
        for (int s = 0; s < 16; ++s) {
            int o = s_r + s * 4;                     // 0..63
            int k = s_c;                             // 0..63
            Wt[k * P + o] = Wh[o * D + kc * KC + k];
        }

        // ---- Stage At[k][m] = x[b0+m][xrow][k] ----
#pragma unroll
        for (int s = 0; s < 16; ++s) {
            int m = s_r + s * 4;                     // 0..63
            int k = s_c;                             // 0..63
            At[k * P + m] = xbase[(size_t)(b0 + m) * (H_IN * W_IN) + k];
        }

        __syncthreads();

        // ---- 4x4 register-tile GEMM over this chunk ----
        const float* a_ptr = At + ty * 4;
        const float* w_ptr = Wt + tx * 4;
#pragma unroll 8
        for (int k = 0; k < KC; ++k) {
            float4 a = *reinterpret_cast<const float4*>(a_ptr + k * P);
            float4 w = *reinterpret_cast<const float4*>(w_ptr + k * P);
            acc[0][0] += a.x * w.x; acc[0][1] += a.x * w.y; acc[0][2] += a.x * w.z; acc[0][3] += a.x * w.w;
            acc[1][0] += a.y * w.x; acc[1][1] += a.y * w.y; acc[1][2] += a.y * w.z; acc[1][3] += a.y * w.w;
            acc[2][0] += a.z * w.x; acc[2][1] += a.z * w.y; acc[2][2] += a.z * w.z; acc[2][3] += a.z * w.w;
            acc[3][0] += a.w * w.x; acc[3][1] += a.w * w.y; acc[3][2] += a.w * w.z; acc[3][3] += a.w * w.w;
        }

        __syncthreads();
    }

    // ---- Epilogue: add bias, write out[b][h][o] ----
    float bv[4];
#pragma unroll
    for (int j = 0; j < 4; ++j)
        bv[j] = bias[h * W_OUT + tx * 4 + j];

#pragma unroll
    for (int i = 0; i < 4; ++i) {
        int m = b0 + ty * 4 + i;
        float4 v;
        v.x = acc[i][0] + bv[0];
        v.y = acc[i][1] + bv[1];
        v.z = acc[i][2] + bv[2];
        v.w = acc[i][3] + bv[3];
        *reinterpret_cast<float4*>(
            out + ((size_t)m * H_OUT + h) * W_OUT + tx * 4) = v;
    }
}

} // namespace asl

extern "C" void kernel_launch(void* const* d_in, const int* in_sizes, int n_in,
                              void* d_out, int out_size) {
    const float* x      = (const float*)d_in[0];
    const int*   mask32 = (const int*)d_in[1];   // int32 or int64 (auto-detected)
    const float* W      = (const float*)d_in[2];
    const float* bias   = (const float*)d_in[3];
    float*       out    = (float*)d_out;

    dim3 grid(asl::B_SZ / asl::BM, asl::H_OUT);   // (8, 256)
    asl::sparse_linear_kernel<<<grid, asl::THREADS>>>(x, mask32, W, bias, out);
}

// round 5
// speedup vs baseline: 1.3859x; 1.3859x over previous
#include <cuda_runtime.h>
#include <cuda_bf16.h>
#include <cstdint>

// out[b,h,o] = sum_d gathered[b,h,d] * W[h,o,d] + bias[h,o]
// gathered[b,h, 64*k + w] = x[b, mask[h,k], w]
// x:(512,128,64) f32, mask:(256,4) i32 (declared i64; JAX x64-off), W:(256,64,256) f32,
// b:(256,64) f32, out:(512,256,64) f32.
//
// Plan: pre-split x and W into bf16 hi/lo pair-packed scratch (device globals),
// then mma.sync m16n8k16 bf16 3-pass GEMM: D = Ahi*Whi + Alo*Whi + Ahi*Wlo.
// (tcgen05 is unavailable: harness PTX targets plain sm_103.)

namespace asl {

constexpr int B_SZ = 512, H_IN = 128, W_IN = 64, H_OUT = 256, W_OUT = 64;
constexpr int KSEL = 4, D = 256;
constexpr int BM = 64;          // batch rows per CTA
constexpr int KC = 64;          // k-chunk = one gathered x row
constexpr int THREADS = 256;    // 8 warps; warp tile m32 x n16
constexpr int PITCH = 34;       // 32-bit words per smem row (32 data + 2 pad)

constexpr int XPAIRS = B_SZ * H_IN * W_IN / 2;   // 2,097,152
constexpr int WPAIRS = H_OUT * W_OUT * D / 2;    // 2,097,152

// Scratch: pair-packed bf16 (two consecutive-k elements per uint32).
__device__ uint32_t g_xhi[XPAIRS];
__device__ uint32_t g_xlo[XPAIRS];
__device__ uint32_t g_whi[WPAIRS];
__device__ uint32_t g_wlo[WPAIRS];

__device__ __forceinline__ uint32_t pack2(float a, float b) {
    __nv_bfloat162 t = __floats2bfloat162_rn(a, b);   // .x -> low 16 bits
    return *reinterpret_cast<uint32_t*>(&t);
}

__global__ void split_kernel(const float* __restrict__ src,
                             uint32_t* __restrict__ hi,
                             uint32_t* __restrict__ lo, int npairs) {
    int i = blockIdx.x * blockDim.x + threadIdx.x;
    int stride = gridDim.x * blockDim.x;
    for (; i < npairs; i += stride) {
        float2 v = reinterpret_cast<const float2*>(src)[i];
        float hx = __bfloat162float(__float2bfloat16_rn(v.x));
        float hy = __bfloat162float(__float2bfloat16_rn(v.y));
        hi[i] = pack2(hx, hy);
        lo[i] = pack2(v.x - hx, v.y - hy);
    }
}

// mask buffer may be i32 or i64 LE (values < 128 => every odd word 0)
__device__ __forceinline__ bool mask_is_i64(const int* m32) {
    int acc = 0;
#pragma unroll
    for (int i = 0; i < 16; ++i) acc |= m32[2 * i + 1];
    return acc == 0;
}
__device__ __forceinline__ int mask_val(const int* m32, bool is64, int idx) {
    int v = is64 ? m32[2 * idx] : m32[idx];
    return min(max(v, 0), H_IN - 1);
}

__device__ __forceinline__ void mma16816(float* c, const uint32_t* a, const uint32_t* b) {
    asm volatile(
        "mma.sync.aligned.m16n8k16.row.col.f32.bf16.bf16.f32 "
        "{%0,%1,%2,%3}, {%4,%5,%6,%7}, {%8,%9}, {%0,%1,%2,%3};"
        : "+f"(c[0]), "+f"(c[1]), "+f"(c[2]), "+f"(c[3])
        : "r"(a[0]), "r"(a[1]), "r"(a[2]), "r"(a[3]), "r"(b[0]), "r"(b[1]));
}

__global__ __launch_bounds__(THREADS)
void gemm_kernel(const int* __restrict__ mask32,
                 const float* __restrict__ bias,
                 float* __restrict__ out) {
    __shared__ uint32_t sAhi[BM * PITCH];
    __shared__ uint32_t sAlo[BM * PITCH];
    __shared__ uint32_t sWhi[W_OUT * PITCH];
    __shared__ uint32_t sWlo[W_OUT * PITCH];

    const int h  = blockIdx.y;
    const int b0 = blockIdx.x * BM;
    const int t    = threadIdx.x;
    const int wid  = t >> 5;
    const int lane = t & 31;
    const int g  = lane >> 2;     // fragment row/col group
    const int tq = lane & 3;      // fragment k sub-index
    const int wm = wid & 1;       // warp m-offset (0/1 -> rows 0/32)
    const int wn = wid >> 1;      // warp n-offset (0..3 -> cols 0/16/32/48)

    const bool m64 = mask_is_i64(mask32);

    float acc[2][2][4];
#pragma unroll
    for (int a = 0; a < 2; ++a)
#pragma unroll
        for (int b = 0; b < 2; ++b)
#pragma unroll
            for (int c = 0; c < 4; ++c) acc[a][b][c] = 0.0f;

#pragma unroll
    for (int kc = 0; kc < KSEL; ++kc) {
        const int xrow = mask_val(mask32, m64, h * KSEL + kc);

        // ---- stage A (64 rows x 32 words) and W (64 rows x 32 words) ----
#pragma unroll
        for (int i = 0; i < 8; ++i) {
            int idx = t + i * THREADS;     // 0..2047
            int r = idx >> 5, w = idx & 31;
            int asrc = ((b0 + r) * H_IN + xrow) * 32 + w;
            sAhi[r * PITCH + w] = g_xhi[asrc];
            sAlo[r * PITCH + w] = g_xlo[asrc];
            int wsrc = (h * W_OUT + r) * 128 + kc * 32 + w;
            sWhi[r * PITCH + w] = g_whi[wsrc];
            sWlo[r * PITCH + w] = g_wlo[wsrc];
        }
        __syncthreads();

        // ---- 4 k16-steps x 3 passes x 4 mmas ----
#pragma unroll
        for (int ks = 0; ks < 4; ++ks) {
            const int aw = ks * 8 + tq;
            uint32_t ah[8], al[8], bh[4], bl[4];
#pragma unroll
            for (int mf = 0; mf < 2; ++mf) {
                int r0 = (wm * 32 + mf * 16 + g) * PITCH;
                int r1 = r0 + 8 * PITCH;
                ah[mf * 4 + 0] = sAhi[r0 + aw];
                ah[mf * 4 + 1] = sAhi[r1 + aw];
                ah[mf * 4 + 2] = sAhi[r0 + aw + 4];
                ah[mf * 4 + 3] = sAhi[r1 + aw + 4];
                al[mf * 4 + 0] = sAlo[r0 + aw];
                al[mf * 4 + 1] = sAlo[r1 + aw];
                al[mf * 4 + 2] = sAlo[r0 + aw + 4];
                al[mf * 4 + 3] = sAlo[r1 + aw + 4];
            }
#pragma unroll
            for (int nf = 0; nf < 2; ++nf) {
                int r = (wn * 16 + nf * 8 + g) * PITCH;
                bh[nf * 2 + 0] = sWhi[r + aw];
                bh[nf * 2 + 1] = sWhi[r + aw + 4];
                bl[nf * 2 + 0] = sWlo[r + aw];
                bl[nf * 2 + 1] = sWlo[r + aw + 4];
            }
#pragma unroll
            for (int mf = 0; mf < 2; ++mf)
#pragma unroll
                for (int nf = 0; nf < 2; ++nf) {
                    mma16816(acc[mf][nf], &ah[mf * 4], &bh[nf * 2]);
                    mma16816(acc[mf][nf], &al[mf * 4], &bh[nf * 2]);
                    mma16816(acc[mf][nf], &ah[mf * 4], &bl[nf * 2]);
                }
        }
        __syncthreads();
    }

    // ---- epilogue: c-frag (g = row, 2t = col), add bias, float2 stores ----
#pragma unroll
    for (int nf = 0; nf < 2; ++nf) {
        int col = wn * 16 + nf * 8 + tq * 2;
        float bx = bias[h * W_OUT + col];
        float by = bias[h * W_OUT + col + 1];
#pragma unroll
        for (int mf = 0; mf < 2; ++mf) {
            int row0 = b0 + wm * 32 + mf * 16 + g;
            float2 v0 = {acc[mf][nf][0] + bx, acc[mf][nf][1] + by};
            float2 v1 = {acc[mf][nf][2] + bx, acc[mf][nf][3] + by};
            *reinterpret_cast<float2*>(
                out + ((size_t)row0 * H_OUT + h) * W_OUT + col) = v0;
            *reinterpret_cast<float2*>(
                out + ((size_t)(row0 + 8) * H_OUT + h) * W_OUT + col) = v1;
        }
    }
}

} // namespace asl

extern "C" void kernel_launch(void* const* d_in, const int* in_sizes, int n_in,
                              void* d_out, int out_size) {
    const float* x      = (const float*)d_in[0];
    const int*   mask32 = (const int*)d_in[1];
    const float* W      = (const float*)d_in[2];
    const float* bias   = (const float*)d_in[3];
    float*       out    = (float*)d_out;

    uint32_t *xhi, *xlo, *whi, *wlo;
    cudaGetSymbolAddress((void**)&xhi, asl::g_xhi);
    cudaGetSymbolAddress((void**)&xlo, asl::g_xlo);
    cudaGetSymbolAddress((void**)&whi, asl::g_whi);
    cudaGetSymbolAddress((void**)&wlo, asl::g_wlo);

    asl::split_kernel<<<2048, 256>>>(x, xhi, xlo, asl::XPAIRS);
    asl::split_kernel<<<2048, 256>>>(W, whi, wlo, asl::WPAIRS);

    dim3 grid(asl::B_SZ / asl::BM, asl::H_OUT);   // (8, 256)
    asl::gemm_kernel<<<grid, asl::THREADS>>>(mask32, bias, out);
}

// round 6
// speedup vs baseline: 2.1206x; 1.5302x over previous
#include <cuda_runtime.h>
#include <cuda_bf16.h>
#include <cstdint>

// out[b,h,o] = sum_d gathered[b,h,d] * W[h,o,d] + bias[h,o]
// gathered[b,h, 64*k + w] = x[b, mask[h,k], w]
// x:(512,128,64) f32, mask:(256,4) i32 (declared i64; JAX x64-off),
// W:(256,64,256) f32, b:(256,64) f32, out:(512,256,64) f32.
//
// bf16 hi/lo split scratch + mma.sync m16n8k16 3-pass GEMM
// (D = Ahi*Whi + Alo*Whi + Ahi*Wlo), fragments via ldmatrix.x4.

namespace asl {

constexpr int B_SZ = 512, H_IN = 128, W_IN = 64, H_OUT = 256, W_OUT = 64;
constexpr int KSEL = 4, D = 256;
constexpr int BM = 64;           // batch rows per CTA
constexpr int THREADS = 256;     // 8 warps; warp tile m32 x n16
constexpr int PITCH = 36;        // words/row: bank-shift 4 => conflict-free ldmatrix

constexpr int XPAIRS = B_SZ * H_IN * W_IN / 2;   // 2,097,152
constexpr int WPAIRS = H_OUT * W_OUT * D / 2;    // 2,097,152

__device__ uint32_t g_xhi[XPAIRS];
__device__ uint32_t g_xlo[XPAIRS];
__device__ uint32_t g_whi[WPAIRS];
__device__ uint32_t g_wlo[WPAIRS];

__device__ __forceinline__ uint32_t pack2(float a, float b) {
    __nv_bfloat162 t = __floats2bfloat162_rn(a, b);
    return *reinterpret_cast<uint32_t*>(&t);
}

// One launch splits both x and W into bf16 hi/lo pair-packed scratch.
__global__ void split_kernel(const float* __restrict__ xsrc,
                             const float* __restrict__ wsrc) {
    int i = blockIdx.x * blockDim.x + threadIdx.x;
    int stride = gridDim.x * blockDim.x;
    for (; i < XPAIRS + WPAIRS; i += stride) {
        const float2* s;
        uint32_t *hi, *lo;
        int j;
        if (i < XPAIRS) {
            s = reinterpret_cast<const float2*>(xsrc); j = i;
            hi = g_xhi; lo = g_xlo;
        } else {
            s = reinterpret_cast<const float2*>(wsrc); j = i - XPAIRS;
            hi = g_whi; lo = g_wlo;
        }
        float2 v = s[j];
        float hx = __bfloat162float(__float2bfloat16_rn(v.x));
        float hy = __bfloat162float(__float2bfloat16_rn(v.y));
        hi[j] = pack2(hx, hy);
        lo[j] = pack2(v.x - hx, v.y - hy);
    }
}

__device__ __forceinline__ bool mask_is_i64(const int* m32) {
    int acc = 0;
#pragma unroll
    for (int i = 0; i < 16; ++i) acc |= m32[2 * i + 1];
    return acc == 0;
}
__device__ __forceinline__ int mask_val(const int* m32, bool is64, int idx) {
    int v = is64 ? m32[2 * idx] : m32[idx];
    return min(max(v, 0), H_IN - 1);
}

__device__ __forceinline__ void mma16816(float* c, const uint32_t* a, const uint32_t* b) {
    asm volatile(
        "mma.sync.aligned.m16n8k16.row.col.f32.bf16.bf16.f32 "
        "{%0,%1,%2,%3}, {%4,%5,%6,%7}, {%8,%9}, {%0,%1,%2,%3};"
        : "+f"(c[0]), "+f"(c[1]), "+f"(c[2]), "+f"(c[3])
        : "r"(a[0]), "r"(a[1]), "r"(a[2]), "r"(a[3]), "r"(b[0]), "r"(b[1]));
}

__device__ __forceinline__ void ldsm4(uint32_t* r, uint32_t saddr) {
    asm volatile("ldmatrix.sync.aligned.m8n8.x4.shared.b16 {%0,%1,%2,%3}, [%4];"
                 : "=r"(r[0]), "=r"(r[1]), "=r"(r[2]), "=r"(r[3]) : "r"(saddr));
}

__device__ __forceinline__ uint32_t smem_u32(const void* p) {
    uint32_t a;
    asm("{ .reg .u64 t; cvta.to.shared.u64 t, %1; cvt.u32.u64 %0, t; }" : "=r"(a) : "l"(p));
    return a;
}

__global__ __launch_bounds__(THREADS)
void gemm_kernel(const int* __restrict__ mask32,
                 const float* __restrict__ bias,
                 float* __restrict__ out) {
    __shared__ alignas(16) uint32_t sAhi[BM * PITCH];
    __shared__ alignas(16) uint32_t sAlo[BM * PITCH];
    __shared__ alignas(16) uint32_t sWhi[W_OUT * PITCH];
    __shared__ alignas(16) uint32_t sWlo[W_OUT * PITCH];

    const int h  = blockIdx.y;
    const int b0 = blockIdx.x * BM;
    const int t    = threadIdx.x;
    const int wid  = t >> 5;
    const int lane = t & 31;
    const int g  = lane >> 2;
    const int tq = lane & 3;
    const int wm = wid & 1;       // rows 0 / 32
    const int wn = wid >> 1;      // cols 0/16/32/48

    const bool m64 = mask_is_i64(mask32);

    // ldmatrix lane addresses (byte offsets within tiles), excluding ks term.
    // A (x4, matrices: (r0-7,k0-7),(r8-15,k0-7),(r0-7,k+8),(r8-15,k+8)):
    const int a_row  = (lane & 15);
    const int a_koff = (lane >> 4) * 16;
    // B (x4, matrices: (n0-7,k0-7),(n0-7,k+8),(n8-15,k0-7),(n8-15,k+8)):
    const int b_row  = (lane & 7) + (lane >> 4) * 8;
    const int b_koff = ((lane >> 3) & 1) * 16;

    const uint32_t aHiB = smem_u32(sAhi) + (wm * 32 + a_row) * (PITCH * 4) + a_koff;
    const uint32_t aLoB = smem_u32(sAlo) + (wm * 32 + a_row) * (PITCH * 4) + a_koff;
    const uint32_t wHiB = smem_u32(sWhi) + (wn * 16 + b_row) * (PITCH * 4) + b_koff;
    const uint32_t wLoB = smem_u32(sWlo) + (wn * 16 + b_row) * (PITCH * 4) + b_koff;

    float acc[2][2][4];
#pragma unroll
    for (int a = 0; a < 2; ++a)
#pragma unroll
        for (int b = 0; b < 2; ++b)
#pragma unroll
            for (int c = 0; c < 4; ++c) acc[a][b][c] = 0.0f;

#pragma unroll
    for (int kc = 0; kc < KSEL; ++kc) {
        const int xrow = mask_val(mask32, m64, h * KSEL + kc);

        // ---- stage via uint4: 64 rows x 8 uint4 per array ----
#pragma unroll
        for (int i = 0; i < 2; ++i) {
            int idx = t + i * THREADS;        // 0..511
            int r = idx >> 3, c = idx & 7;
            uint32_t so = (uint32_t)(r * (PITCH * 4) + c * 16);  // byte offset
            int asrc = ((b0 + r) * H_IN + xrow) * 8 + c;         // uint4 index
            *reinterpret_cast<uint4*>(reinterpret_cast<char*>(sAhi) + so) =
                reinterpret_cast<const uint4*>(g_xhi)[asrc];
            *reinterpret_cast<uint4*>(reinterpret_cast<char*>(sAlo) + so) =
                reinterpret_cast<const uint4*>(g_xlo)[asrc];
            int wsrc = (h * W_OUT + r) * 32 + kc * 8 + c;
            *reinterpret_cast<uint4*>(reinterpret_cast<char*>(sWhi) + so) =
                reinterpret_cast<const uint4*>(g_whi)[wsrc];
            *reinterpret_cast<uint4*>(reinterpret_cast<char*>(sWlo) + so) =
                reinterpret_cast<const uint4*>(g_wlo)[wsrc];
        }
        __syncthreads();

        // ---- 4 k16-steps: 6 ldmatrix.x4 + 12 mma each ----
#pragma unroll
        for (int ks = 0; ks < 4; ++ks) {
            const uint32_t ko = ks * 32;      // 16 bf16 = 32B per k-step
            uint32_t ah[8], al[8], bh[4], bl[4];
            ldsm4(&ah[0], aHiB + ko);
            ldsm4(&ah[4], aHiB + 16 * (PITCH * 4) + ko);
            ldsm4(&al[0], aLoB + ko);
            ldsm4(&al[4], aLoB + 16 * (PITCH * 4) + ko);
            ldsm4(bh, wHiB + ko);
            ldsm4(bl, wLoB + ko);
#pragma unroll
            for (int mf = 0; mf < 2; ++mf)
#pragma unroll
                for (int nf = 0; nf < 2; ++nf) {
                    mma16816(acc[mf][nf], &ah[mf * 4], &bh[nf * 2]);
                    mma16816(acc[mf][nf], &al[mf * 4], &bh[nf * 2]);
                    mma16816(acc[mf][nf], &ah[mf * 4], &bl[nf * 2]);
                }
        }
        __syncthreads();
    }

    // ---- epilogue ----
#pragma unroll
    for (int nf = 0; nf < 2; ++nf) {
        int col = wn * 16 + nf * 8 + tq * 2;
        float bx = bias[h * W_OUT + col];
        float by = bias[h * W_OUT + col + 1];
#pragma unroll
        for (int mf = 0; mf < 2; ++mf) {
            int row0 = b0 + wm * 32 + mf * 16 + g;
            float2 v0 = {acc[mf][nf][0] + bx, acc[mf][nf][1] + by};
            float2 v1 = {acc[mf][nf][2] + bx, acc[mf][nf][3] + by};
            *reinterpret_cast<float2*>(
                out + ((size_t)row0 * H_OUT + h) * W_OUT + col) = v0;
            *reinterpret_cast<float2*>(
                out + ((size_t)(row0 + 8) * H_OUT + h) * W_OUT + col) = v1;
        }
    }
}

} // namespace asl

extern "C" void kernel_launch(void* const* d_in, const int* in_sizes, int n_in,
                              void* d_out, int out_size) {
    const float* x      = (const float*)d_in[0];
    const int*   mask32 = (const int*)d_in[1];
    const float* W      = (const float*)d_in[2];
    const float* bias   = (const float*)d_in[3];
    float*       out    = (float*)d_out;

    asl::split_kernel<<<4096, 256>>>(x, W);

    dim3 grid(asl::B_SZ / asl::BM, asl::H_OUT);   // (8, 256)
    asl::gemm_kernel<<<grid, asl::THREADS>>>(mask32, bias, out);
}

// round 7
// speedup vs baseline: 2.3296x; 1.0986x over previous
#include <cuda_runtime.h>
#include <cuda_bf16.h>
#include <cstdint>

// out[b,h,o] = sum_d gathered[b,h,d] * W[h,o,d] + bias[h,o]
// gathered[b,h, 64*k + w] = x[b, mask[h,k], w]
// x:(512,128,64) f32, mask:(256,4) i32 (declared i64; JAX x64-off),
// W:(256,64,256) f32, b:(256,64) f32, out:(512,256,64) f32.
//
// bf16 hi/lo split scratch + mma.sync m16n8k16 3-pass GEMM
// (D = Ahi*Whi + Alo*Whi + Ahi*Wlo). 4 warps, warp tile m32 x n32
// (2x2 warp grid) to halve A-fragment LDSM redundancy vs 8-warp m32n16.

namespace asl {

constexpr int B_SZ = 512, H_IN = 128, W_IN = 64, H_OUT = 256, W_OUT = 64;
constexpr int KSEL = 4, D = 256;
constexpr int BM = 64;           // batch rows per CTA
constexpr int THREADS = 128;     // 4 warps; warp tile m32 x n32
constexpr int PITCH = 36;        // words/row: bank-shift 4 => conflict-free ldmatrix

constexpr int XPAIRS = B_SZ * H_IN * W_IN / 2;   // 2,097,152
constexpr int WPAIRS = H_OUT * W_OUT * D / 2;    // 2,097,152

__device__ uint32_t g_xhi[XPAIRS];
__device__ uint32_t g_xlo[XPAIRS];
__device__ uint32_t g_whi[WPAIRS];
__device__ uint32_t g_wlo[WPAIRS];

__device__ __forceinline__ uint32_t pack2(float a, float b) {
    __nv_bfloat162 t = __floats2bfloat162_rn(a, b);
    return *reinterpret_cast<uint32_t*>(&t);
}

// One launch splits both x and W (float4 per iteration).
__global__ void split_kernel(const float* __restrict__ xsrc,
                             const float* __restrict__ wsrc) {
    constexpr int XQ = XPAIRS / 2, WQ = WPAIRS / 2;
    int i = blockIdx.x * blockDim.x + threadIdx.x;
    int stride = gridDim.x * blockDim.x;
    for (; i < XQ + WQ; i += stride) {
        const float4* s;
        uint32_t *hi, *lo;
        int j;
        if (i < XQ) { s = reinterpret_cast<const float4*>(xsrc); j = i; hi = g_xhi; lo = g_xlo; }
        else        { s = reinterpret_cast<const float4*>(wsrc); j = i - XQ; hi = g_whi; lo = g_wlo; }
        float4 v = s[j];
        float hx = __bfloat162float(__float2bfloat16_rn(v.x));
        float hy = __bfloat162float(__float2bfloat16_rn(v.y));
        float hz = __bfloat162float(__float2bfloat16_rn(v.z));
        float hw = __bfloat162float(__float2bfloat16_rn(v.w));
        uint2 hv = {pack2(hx, hy), pack2(hz, hw)};
        uint2 lv = {pack2(v.x - hx, v.y - hy), pack2(v.z - hz, v.w - hw)};
        reinterpret_cast<uint2*>(hi)[j] = hv;
        reinterpret_cast<uint2*>(lo)[j] = lv;
    }
}

__device__ __forceinline__ bool mask_is_i64(const int* m32) {
    int acc = 0;
#pragma unroll
    for (int i = 0; i < 16; ++i) acc |= m32[2 * i + 1];
    return acc == 0;
}
__device__ __forceinline__ int mask_val(const int* m32, bool is64, int idx) {
    int v = is64 ? m32[2 * idx] : m32[idx];
    return min(max(v, 0), H_IN - 1);
}

__device__ __forceinline__ void mma16816(float* c, const uint32_t* a, const uint32_t* b) {
    asm volatile(
        "mma.sync.aligned.m16n8k16.row.col.f32.bf16.bf16.f32 "
        "{%0,%1,%2,%3}, {%4,%5,%6,%7}, {%8,%9}, {%0,%1,%2,%3};"
        : "+f"(c[0]), "+f"(c[1]), "+f"(c[2]), "+f"(c[3])
        : "r"(a[0]), "r"(a[1]), "r"(a[2]), "r"(a[3]), "r"(b[0]), "r"(b[1]));
}

__device__ __forceinline__ void ldsm4(uint32_t* r, uint32_t saddr) {
    asm volatile("ldmatrix.sync.aligned.m8n8.x4.shared.b16 {%0,%1,%2,%3}, [%4];"
                 : "=r"(r[0]), "=r"(r[1]), "=r"(r[2]), "=r"(r[3]) : "r"(saddr));
}

__device__ __forceinline__ uint32_t smem_u32(const void* p) {
    uint32_t a;
    asm("{ .reg .u64 t; cvta.to.shared.u64 t, %1; cvt.u32.u64 %0, t; }" : "=r"(a) : "l"(p));
    return a;
}

__global__ __launch_bounds__(THREADS)
void gemm_kernel(const int* __restrict__ mask32,
                 const float* __restrict__ bias,
                 float* __restrict__ out) {
    __shared__ alignas(16) uint32_t sAhi[BM * PITCH];
    __shared__ alignas(16) uint32_t sAlo[BM * PITCH];
    __shared__ alignas(16) uint32_t sWhi[W_OUT * PITCH];
    __shared__ alignas(16) uint32_t sWlo[W_OUT * PITCH];

    const int h  = blockIdx.y;
    const int b0 = blockIdx.x * BM;
    const int t    = threadIdx.x;
    const int wid  = t >> 5;
    const int lane = t & 31;
    const int g  = lane >> 2;
    const int tq = lane & 3;
    const int wm = wid & 1;       // rows 0 / 32
    const int wn = wid >> 1;      // cols 0 / 32

    const bool m64 = mask_is_i64(mask32);

    // ldmatrix lane addressing (byte offsets), excluding the k-step term.
    // A x4 -> matrices (r0-7,k0-7),(r8-15,k0-7),(r0-7,k8-15),(r8-15,k8-15)
    const int a_row  = (lane & 15);
    const int a_koff = (lane >> 4) * 16;
    // B x4 -> matrices (n0-7,k0-7),(n0-7,k8-15),(n8-15,k0-7),(n8-15,k8-15)
    const int b_row  = (lane & 7) + (lane >> 4) * 8;
    const int b_koff = ((lane >> 3) & 1) * 16;

    const uint32_t aHiB = smem_u32(sAhi) + (wm * 32 + a_row) * (PITCH * 4) + a_koff;
    const uint32_t aLoB = smem_u32(sAlo) + (wm * 32 + a_row) * (PITCH * 4) + a_koff;
    const uint32_t wHiB = smem_u32(sWhi) + (wn * 32 + b_row) * (PITCH * 4) + b_koff;
    const uint32_t wLoB = smem_u32(sWlo) + (wn * 32 + b_row) * (PITCH * 4) + b_koff;

    float acc[2][4][4];
#pragma unroll
    for (int a = 0; a < 2; ++a)
#pragma unroll
        for (int b = 0; b < 4; ++b)
#pragma unroll
            for (int c = 0; c < 4; ++c) acc[a][b][c] = 0.0f;

#pragma unroll
    for (int kc = 0; kc < KSEL; ++kc) {
        const int xrow = mask_val(mask32, m64, h * KSEL + kc);

        // ---- stage via uint4: 64 rows x 8 uint4 per array ----
#pragma unroll
        for (int i = 0; i < 4; ++i) {
            int idx = t + i * THREADS;        // 0..511
            int r = idx >> 3, c = idx & 7;
            uint32_t so = (uint32_t)(r * (PITCH * 4) + c * 16);  // byte offset
            int asrc = ((b0 + r) * H_IN + xrow) * 8 + c;         // uint4 index
            *reinterpret_cast<uint4*>(reinterpret_cast<char*>(sAhi) + so) =
                reinterpret_cast<const uint4*>(g_xhi)[asrc];
            *reinterpret_cast<uint4*>(reinterpret_cast<char*>(sAlo) + so) =
                reinterpret_cast<const uint4*>(g_xlo)[asrc];
            int wsrc = (h * W_OUT + r) * 32 + kc * 8 + c;
            *reinterpret_cast<uint4*>(reinterpret_cast<char*>(sWhi) + so) =
                reinterpret_cast<const uint4*>(g_whi)[wsrc];
            *reinterpret_cast<uint4*>(reinterpret_cast<char*>(sWlo) + so) =
                reinterpret_cast<const uint4*>(g_wlo)[wsrc];
        }
        __syncthreads();

        // ---- 4 k16-steps: 8 ldmatrix.x4 + 24 mma each ----
#pragma unroll
        for (int ks = 0; ks < 4; ++ks) {
            const uint32_t ko = ks * 32;      // 16 bf16 = 32B per k-step
            uint32_t ah[8], al[8], bh[8], bl[8];
            ldsm4(&ah[0], aHiB + ko);
            ldsm4(&ah[4], aHiB + 16 * (PITCH * 4) + ko);
            ldsm4(&al[0], aLoB + ko);
            ldsm4(&al[4], aLoB + 16 * (PITCH * 4) + ko);
            ldsm4(&bh[0], wHiB + ko);
            ldsm4(&bh[4], wHiB + 16 * (PITCH * 4) + ko);
            ldsm4(&bl[0], wLoB + ko);
            ldsm4(&bl[4], wLoB + 16 * (PITCH * 4) + ko);
#pragma unroll
            for (int mf = 0; mf < 2; ++mf)
#pragma unroll
                for (int nf = 0; nf < 4; ++nf) {
                    mma16816(acc[mf][nf], &ah[mf * 4], &bh[nf * 2]);
                    mma16816(acc[mf][nf], &al[mf * 4], &bh[nf * 2]);
                    mma16816(acc[mf][nf], &ah[mf * 4], &bl[nf * 2]);
                }
        }
        __syncthreads();
    }

    // ---- epilogue: add bias, float2 stores ----
#pragma unroll
    for (int nf = 0; nf < 4; ++nf) {
        int col = wn * 32 + nf * 8 + tq * 2;
        float bx = bias[h * W_OUT + col];
        float by = bias[h * W_OUT + col + 1];
#pragma unroll
        for (int mf = 0; mf < 2; ++mf) {
            int row0 = b0 + wm * 32 + mf * 16 + g;
            float2 v0 = {acc[mf][nf][0] + bx, acc[mf][nf][1] + by};
            float2 v1 = {acc[mf][nf][2] + bx, acc[mf][nf][3] + by};
            *reinterpret_cast<float2*>(
                out + ((size_t)row0 * H_OUT + h) * W_OUT + col) = v0;
            *reinterpret_cast<float2*>(
                out + ((size_t)(row0 + 8) * H_OUT + h) * W_OUT + col) = v1;
        }
    }
}

} // namespace asl

extern "C" void kernel_launch(void* const* d_in, const int* in_sizes, int n_in,
                              void* d_out, int out_size) {
    const float* x      = (const float*)d_in[0];
    const int*   mask32 = (const int*)d_in[1];
    const float* W      = (const float*)d_in[2];
    const float* bias   = (const float*)d_in[3];
    float*       out    = (float*)d_out;

    asl::split_kernel<<<4096, 256>>>(x, W);

    dim3 grid(asl::B_SZ / asl::BM, asl::H_OUT);   // (8, 256)
    asl::gemm_kernel<<<grid, asl::THREADS>>>(mask32, bias, out);
}

// round 8
// speedup vs baseline: 2.5891x; 1.1114x over previous
#include <cuda_runtime.h>
#include <cuda_bf16.h>
#include <cstdint>

// out[b,h,o] = sum_d gathered[b,h,d] * W[h,o,d] + bias[h,o]
// gathered[b,h, 64*k + w] = x[b, mask[h,k], w]
// x:(512,128,64) f32, mask:(256,4) i32 (declared i64; JAX x64-off),
// W:(256,64,256) f32, b:(256,64) f32, out:(512,256,64) f32.
//
// Single fused kernel: stage f32 -> bf16 hi/lo in smem (XOR-swizzled),
// 3-pass mma.sync m16n8k16 (D = Ahi*Whi + Alo*Whi + Ahi*Wlo).
// CTA tile m128 x n64, 4 warps of m64 x n32.

namespace asl {

constexpr int B_SZ = 512, H_IN = 128, W_IN = 64, H_OUT = 256, W_OUT = 64;
constexpr int KSEL = 4, D = 256;
constexpr int BM = 128;          // batch rows per CTA
constexpr int THREADS = 128;     // 4 warps, warp tile m64 x n32

__device__ __forceinline__ bool mask_is_i64(const int* m32) {
    int acc = 0;
#pragma unroll
    for (int i = 0; i < 16; ++i) acc |= m32[2 * i + 1];
    return acc == 0;
}
__device__ __forceinline__ int mask_val(const int* m32, bool is64, int idx) {
    int v = is64 ? m32[2 * idx] : m32[idx];
    return min(max(v, 0), H_IN - 1);
}

__device__ __forceinline__ void mma16816(float* c, const uint32_t* a, const uint32_t* b) {
    asm volatile(
        "mma.sync.aligned.m16n8k16.row.col.f32.bf16.bf16.f32 "
        "{%0,%1,%2,%3}, {%4,%5,%6,%7}, {%8,%9}, {%0,%1,%2,%3};"
        : "+f"(c[0]), "+f"(c[1]), "+f"(c[2]), "+f"(c[3])
        : "r"(a[0]), "r"(a[1]), "r"(a[2]), "r"(a[3]), "r"(b[0]), "r"(b[1]));
}

__device__ __forceinline__ void ldsm4(uint32_t* r, uint32_t saddr) {
    asm volatile("ldmatrix.sync.aligned.m8n8.x4.shared.b16 {%0,%1,%2,%3}, [%4];"
                 : "=r"(r[0]), "=r"(r[1]), "=r"(r[2]), "=r"(r[3]) : "r"(saddr));
}

__device__ __forceinline__ uint32_t smem_u32(const void* p) {
    uint32_t a;
    asm("{ .reg .u64 t; cvta.to.shared.u64 t, %1; cvt.u32.u64 %0, t; }" : "=r"(a) : "l"(p));
    return a;
}

// 8 f32 -> 4x hi-pairs + 4x lo-pairs (pair-packed bf16).
__device__ __forceinline__ void cvt8(float4 v0, float4 v1, uint4& hi, uint4& lo) {
    auto one = [](float p, float q, uint32_t& h, uint32_t& l) {
        __nv_bfloat162 hb = __floats2bfloat162_rn(p, q);
        float hp = __bfloat162float(hb.x), hq = __bfloat162float(hb.y);
        __nv_bfloat162 lb = __floats2bfloat162_rn(p - hp, q - hq);
        h = *reinterpret_cast<uint32_t*>(&hb);
        l = *reinterpret_cast<uint32_t*>(&lb);
    };
    one(v0.x, v0.y, hi.x, lo.x);
    one(v0.z, v0.w, hi.y, lo.y);
    one(v1.x, v1.y, hi.z, lo.z);
    one(v1.z, v1.w, hi.w, lo.w);
}

__global__ __launch_bounds__(THREADS)
void fused_kernel(const float* __restrict__ x,
                  const int* __restrict__ mask32,
                  const float* __restrict__ W,
                  const float* __restrict__ bias,
                  float* __restrict__ out) {
    // Rows of 64 bf16 (128B = 32 words), 16B chunks XOR-swizzled: phys = c ^ (r&7).
    __shared__ alignas(16) uint32_t sAhi[BM * 32];      // 16 KB
    __shared__ alignas(16) uint32_t sAlo[BM * 32];      // 16 KB
    __shared__ alignas(16) uint32_t sWhi[W_OUT * 32];   //  8 KB
    __shared__ alignas(16) uint32_t sWlo[W_OUT * 32];   //  8 KB

    const int h  = blockIdx.y;
    const int b0 = blockIdx.x * BM;
    const int t    = threadIdx.x;
    const int wid  = t >> 5;
    const int lane = t & 31;
    const int g  = lane >> 2;
    const int tq = lane & 3;
    const int wm = wid & 1;       // m offset: wm*64
    const int wn = wid >> 1;      // n offset: wn*32

    const bool m64flag = mask_is_i64(mask32);

    const uint32_t aHiBase = smem_u32(sAhi);
    const uint32_t aLoBase = smem_u32(sAlo);
    const uint32_t wHiBase = smem_u32(sWhi);
    const uint32_t wLoBase = smem_u32(sWlo);

    // ldmatrix lane geometry (fragment row offsets are multiples of 8, so the
    // swizzle XOR term is simply lane&7 for every fragment).
    const int rx   = lane & 7;
    const int a_hi = lane >> 4;           // A: k-chunk +0/+1
    const int b_hi = (lane >> 3) & 1;     // B: k-chunk +0/+1
    uint32_t aRow[4], bRow[2];
#pragma unroll
    for (int mf = 0; mf < 4; ++mf)
        aRow[mf] = (uint32_t)((wm * 64 + mf * 16 + (lane & 15)) * 128);
#pragma unroll
    for (int pr = 0; pr < 2; ++pr)
        bRow[pr] = (uint32_t)((wn * 32 + pr * 16 + (lane & 7) + ((lane >> 4) << 3)) * 128);

    float acc[4][4][4];
#pragma unroll
    for (int a = 0; a < 4; ++a)
#pragma unroll
        for (int b = 0; b < 4; ++b)
#pragma unroll
            for (int c = 0; c < 4; ++c) acc[a][b][c] = 0.0f;

    const float4* xq = reinterpret_cast<const float4*>(x);
    const float4* wq = reinterpret_cast<const float4*>(W);

#pragma unroll
    for (int kc = 0; kc < KSEL; ++kc) {
        const int xrow = mask_val(mask32, m64flag, h * KSEL + kc);

        // ---- stage A: 128 rows x 8 chunks (f32 -> bf16 hi/lo, swizzled) ----
#pragma unroll
        for (int i = 0; i < 8; ++i) {
            int idx = t + i * THREADS;           // 0..1023
            int r = idx >> 3, c = idx & 7;
            long f4 = ((long)(b0 + r) * H_IN + xrow) * 16 + c * 2;
            float4 v0 = xq[f4], v1 = xq[f4 + 1];
            uint4 hi, lo;
            cvt8(v0, v1, hi, lo);
            uint32_t off = (uint32_t)(r * 128 + ((c ^ (r & 7)) << 4));
            *reinterpret_cast<uint4*>(reinterpret_cast<char*>(sAhi) + off) = hi;
            *reinterpret_cast<uint4*>(reinterpret_cast<char*>(sAlo) + off) = lo;
        }
        // ---- stage W: 64 rows x 8 chunks ----
#pragma unroll
        for (int i = 0; i < 4; ++i) {
            int idx = t + i * THREADS;           // 0..511
            int r = idx >> 3, c = idx & 7;
            int f4 = (h * 64 + r) * 64 + kc * 16 + c * 2;
            float4 v0 = wq[f4], v1 = wq[f4 + 1];
            uint4 hi, lo;
            cvt8(v0, v1, hi, lo);
            uint32_t off = (uint32_t)(r * 128 + ((c ^ (r & 7)) << 4));
            *reinterpret_cast<uint4*>(reinterpret_cast<char*>(sWhi) + off) = hi;
            *reinterpret_cast<uint4*>(reinterpret_cast<char*>(sWlo) + off) = lo;
        }
        __syncthreads();

        // ---- 4 k16-steps: 12 ldmatrix.x4 + 48 mma each ----
#pragma unroll
        for (int ks = 0; ks < 4; ++ks) {
            uint32_t ah[16], al[16], bh[8], bl[8];
            const int ks2 = ks * 2;
#pragma unroll
            for (int mf = 0; mf < 4; ++mf) {
                uint32_t off = aRow[mf] + (uint32_t)((((ks2 + a_hi) ^ rx)) << 4);
                ldsm4(&ah[mf * 4], aHiBase + off);
                ldsm4(&al[mf * 4], aLoBase + off);
            }
#pragma unroll
            for (int pr = 0; pr < 2; ++pr) {
                uint32_t off = bRow[pr] + (uint32_t)((((ks2 + b_hi) ^ rx)) << 4);
                ldsm4(&bh[pr * 4], wHiBase + off);
                ldsm4(&bl[pr * 4], wLoBase + off);
            }
#pragma unroll
            for (int mf = 0; mf < 4; ++mf)
#pragma unroll
                for (int nf = 0; nf < 4; ++nf) {
                    mma16816(acc[mf][nf], &ah[mf * 4], &bh[nf * 2]);
                    mma16816(acc[mf][nf], &al[mf * 4], &bh[nf * 2]);
                    mma16816(acc[mf][nf], &ah[mf * 4], &bl[nf * 2]);
                }
        }
        __syncthreads();
    }

    // ---- epilogue: add bias, float2 stores ----
#pragma unroll
    for (int nf = 0; nf < 4; ++nf) {
        int col = wn * 32 + nf * 8 + tq * 2;
        float bx = bias[h * W_OUT + col];
        float by = bias[h * W_OUT + col + 1];
#pragma unroll
        for (int mf = 0; mf < 4; ++mf) {
            int row0 = b0 + wm * 64 + mf * 16 + g;
            float2 v0 = {acc[mf][nf][0] + bx, acc[mf][nf][1] + by};
            float2 v1 = {acc[mf][nf][2] + bx, acc[mf][nf][3] + by};
            *reinterpret_cast<float2*>(
                out + ((size_t)row0 * H_OUT + h) * W_OUT + col) = v0;
            *reinterpret_cast<float2*>(
                out + ((size_t)(row0 + 8) * H_OUT + h) * W_OUT + col) = v1;
        }
    }
}

} // namespace asl

extern "C" void kernel_launch(void* const* d_in, const int* in_sizes, int n_in,
                              void* d_out, int out_size) {
    const float* x      = (const float*)d_in[0];
    const int*   mask32 = (const int*)d_in[1];
    const float* W      = (const float*)d_in[2];
    const float* bias   = (const float*)d_in[3];
    float*       out    = (float*)d_out;

    dim3 grid(asl::B_SZ / asl::BM, asl::H_OUT);   // (4, 256)
    asl::fused_kernel<<<grid, asl::THREADS>>>(x, mask32, W, bias, out);
}